// round 13
// baseline (speedup 1.0000x reference)
#include <cuda_runtime.h>
#include <cuda_bf16.h>
#include <cuda_fp16.h>
#include <cstdint>

// ScaledDotProductAttention B=1 H=8 S=2048 D=64, sm_103 base ISA.
// R12 math + CH=128 pipeline granularity: each chunk = 4 sub-blocks of 32 kv
// processed without intermediate barriers (16 barriers total), 3-stage
// KV-only cp.async pipeline (48KB stages). sph/mask straight to registers,
// V single f16 (PV 1 combo), QK bf16 hi/lo 3-combo. p written fp32
// unnormalized in-loop; fused tail normalizes p via L2 re-read.
// d_out = [out 1x8x2048x64 | p_attn 1x8x2048x2048].

#define SQ 2048
#define HD 64
#define NH 8
#define MT 128          // q rows per CTA
#define CH 128          // kv per chunk (pipeline granularity)
#define NSUB 4          // sub-blocks of 32 kv per chunk (compute granularity)
#define NCH (SQ / CH)   // 16
#define THREADS 512

// ---- smem layout (bytes) ----
// stage s at s*STG: khi 0 | klo 16384 | vh 32768   (48KB each, 3 stages)
#define STG   49152
#define S_QHI (2 * STG)                  // Q hi 16KB (prologue only, overlays st2)
#define S_QLO (2 * STG + 16384)          // Q lo 16KB
#define S_TOTAL (3 * STG)                // 147456
// epilogue overlays (stage 0 area)
#define S_OSM 0                          // f32 [8][32][32] = 32KB
#define S_LSM 32768                      // f32 [2][128]

__device__ __nv_bfloat16 g_khi[NH * SQ * HD];
__device__ __nv_bfloat16 g_klo[NH * SQ * HD];
__device__ __half        g_vh [NH * SQ * HD];

__device__ __forceinline__ uint32_t smem_u32(const void* p) {
    uint32_t a;
    asm("{ .reg .u64 t; cvta.to.shared.u64 t, %1; cvt.u32.u64 %0, t; }"
        : "=r"(a) : "l"(p));
    return a;
}
__device__ __forceinline__ void cpa16(uint32_t dst, const void* src) {
    asm volatile("cp.async.cg.shared.global [%0], [%1], 16;"
                 :: "r"(dst), "l"(src));
}
__device__ __forceinline__ void cpa_commit() {
    asm volatile("cp.async.commit_group;" ::: "memory");
}
__device__ __forceinline__ void cpa_wait0() {
    asm volatile("cp.async.wait_group 0;" ::: "memory");
}
__device__ __forceinline__ void cpa_wait1() {
    asm volatile("cp.async.wait_group 1;" ::: "memory");
}
__device__ __forceinline__ void ldsm4(uint32_t* r, uint32_t addr) {
    asm volatile("ldmatrix.sync.aligned.m8n8.x4.shared.b16 {%0,%1,%2,%3}, [%4];"
                 : "=r"(r[0]), "=r"(r[1]), "=r"(r[2]), "=r"(r[3]) : "r"(addr));
}
__device__ __forceinline__ void ldsm4t(uint32_t* r, uint32_t addr) {
    asm volatile("ldmatrix.sync.aligned.m8n8.x4.trans.shared.b16 {%0,%1,%2,%3}, [%4];"
                 : "=r"(r[0]), "=r"(r[1]), "=r"(r[2]), "=r"(r[3]) : "r"(addr));
}
__device__ __forceinline__ void mma_bf16(float* c, const uint32_t* a,
                                         uint32_t b0, uint32_t b1) {
    asm volatile(
        "mma.sync.aligned.m16n8k16.row.col.f32.bf16.bf16.f32 "
        "{%0,%1,%2,%3}, {%4,%5,%6,%7}, {%8,%9}, {%0,%1,%2,%3};"
        : "+f"(c[0]), "+f"(c[1]), "+f"(c[2]), "+f"(c[3])
        : "r"(a[0]), "r"(a[1]), "r"(a[2]), "r"(a[3]), "r"(b0), "r"(b1));
}
__device__ __forceinline__ void mma_f16(float* c, const uint32_t* a,
                                        uint32_t b0, uint32_t b1) {
    asm volatile(
        "mma.sync.aligned.m16n8k16.row.col.f32.f16.f16.f32 "
        "{%0,%1,%2,%3}, {%4,%5,%6,%7}, {%8,%9}, {%0,%1,%2,%3};"
        : "+f"(c[0]), "+f"(c[1]), "+f"(c[2]), "+f"(c[3])
        : "r"(a[0]), "r"(a[1]), "r"(a[2]), "r"(a[3]), "r"(b0), "r"(b1));
}
__device__ __forceinline__ uint32_t bf2u(__nv_bfloat162 x) {
    uint32_t r; *(__nv_bfloat162*)&r = x; return r;
}
__device__ __forceinline__ void split_pack2(float a, float b,
                                            uint32_t& hi, uint32_t& lo) {
    __nv_bfloat162 h = __floats2bfloat162_rn(a, b);
    hi = bf2u(h);
    lo = bf2u(__floats2bfloat162_rn(a - __bfloat162float(h.x),
                                    b - __bfloat162float(h.y)));
}
__device__ __forceinline__ uint32_t h2u(__half2 x) {
    uint32_t r; *(__half2*)&r = x; return r;
}
// 128B-row tiles: SW128-style swizzle
__device__ __forceinline__ uint32_t swz(int row, int colB) {
    return (uint32_t)(((row << 7) + colB) ^ ((row & 7) << 4));
}

// ---------------- prep: K -> bf16 hi/lo, V -> f16 ----------------
__global__ __launch_bounds__(256)
void conv_kv(const float* __restrict__ k, const float* __restrict__ v)
{
    int idx = blockIdx.x * 256 + threadIdx.x;   // over NH*SQ*HD/4
    float4 kf = ((const float4*)k)[idx];
    uint32_t h0, l0, h1, l1;
    split_pack2(kf.x, kf.y, h0, l0);
    split_pack2(kf.z, kf.w, h1, l1);
    ((uint2*)g_khi)[idx] = make_uint2(h0, h1);
    ((uint2*)g_klo)[idx] = make_uint2(l0, l1);
    float4 vf = ((const float4*)v)[idx];
    __half2 v0 = __float22half2_rn(make_float2(vf.x, vf.y));
    __half2 v1 = __float22half2_rn(make_float2(vf.z, vf.w));
    ((uint2*)g_vh)[idx] = make_uint2(h2u(v0), h2u(v1));
}

// ---------------- main fused attention (+ p normalization) ----------------
__global__ __launch_bounds__(THREADS)
void attn_mma(const float* __restrict__ q, const float* __restrict__ sph,
              const int* __restrict__ mask,
              float* __restrict__ out, float* __restrict__ p)
{
    extern __shared__ char smem[];
    const uint32_t sb = smem_u32(smem);
    float* osm  = (float*)(smem + S_OSM);
    float* l_sm = (float*)(smem + S_LSM);

    const int t = threadIdx.x, w = t >> 5, lane = t & 31;
    const int g = lane >> 2, lam = lane & 3;
    const int rt = w & 7;              // row-tile (16 rows)
    const int nh = w >> 3;             // kv-half within each 32-kv sub-block
    const int h = blockIdx.y, q0 = blockIdx.x * MT;
    const int r0 = rt * 16 + g, r1 = r0 + 8;

    const float* qh  = q + ((size_t)h * SQ + q0) * HD;
    const float* sc0 = sph + ((size_t)h * SQ + q0) * SQ;
    const int*   mc0 = mask + ((size_t)h * SQ + q0) * SQ;
    float*       pc0 = p + ((size_t)h * SQ + q0) * SQ;

    const __nv_bfloat16* kh = g_khi + (size_t)h * SQ * HD;
    const __nv_bfloat16* kl = g_klo + (size_t)h * SQ * HD;
    const __half*        vv = g_vh  + (size_t)h * SQ * HD;

    // stage prefetch: 3072 16B units (khi 1024 | klo 1024 | vh 1024)
    auto prefetch = [&](int cc, int st) {
        const uint32_t base = sb + (uint32_t)st * STG;
        #pragma unroll
        for (int it = 0; it < 6; ++it) {
            int idx = t + THREADS * it;
            int arr = idx >> 10;
            int rem = idx & 1023, row = rem >> 3, u = rem & 7;
            const void* src = (arr == 0)
                ? (const void*)(kh + (size_t)(cc + row) * HD + u * 8)
                : (arr == 1)
                ? (const void*)(kl + (size_t)(cc + row) * HD + u * 8)
                : (const void*)(vv + (size_t)(cc + row) * HD + u * 8);
            cpa16(base + arr * 16384 + swz(row, u * 16), src);
        }
        cpa_commit();
    };

    prefetch(0, 0);
    prefetch(CH, 1);

    // ---- prologue: stage Q (x1/8) hi/lo (overlays stage 2), load A-frags ----
    #pragma unroll
    for (int i = 0; i < 4; ++i) {                // 2048 float4 = 128x64
        int idx = t + THREADS * i;
        int row = idx >> 4, gq = idx & 15;
        float4 f = ((const float4*)qh)[idx];
        f.x *= 0.125f; f.y *= 0.125f; f.z *= 0.125f; f.w *= 0.125f;
        uint32_t h0, l0, h1, l1;
        split_pack2(f.x, f.y, h0, l0);
        split_pack2(f.z, f.w, h1, l1);
        uint32_t off = swz(row, gq * 8);
        *(uint2*)(smem + S_QHI + off) = make_uint2(h0, h1);
        *(uint2*)(smem + S_QLO + off) = make_uint2(l0, l1);
    }
    __syncthreads();
    uint32_t ah[4][4], al[4][4];
    {
        int arow = rt * 16 + ((lane >> 3) & 1) * 8 + (lane & 7);
        int acol = ((lane >> 4) & 1) * 16;
        #pragma unroll
        for (int kk = 0; kk < 4; ++kk) {
            uint32_t aoff = swz(arow, acol + kk * 32);
            ldsm4(ah[kk], sb + S_QHI + aoff);
            ldsm4(al[kk], sb + S_QLO + aoff);
        }
    }

    float O[8][4];
    #pragma unroll
    for (int a = 0; a < 8; ++a)
        #pragma unroll
        for (int b = 0; b < 4; ++b) O[a][b] = 0.f;
    float lacc0 = 0.f, lacc1 = 0.f;

    const int ksrow = (lane & 7);                      // K ldsm row-in-tile
    const int kssel = ((lane >> 3) & 1) * 16;
    const int kntad = (lane >> 4);                     // +0/+1 n-tile
    const int vrow  = (lane & 15);                     // V ldsm
    const int vntad = (lane >> 4);
    const int cbase = nh * 16 + lam * 2;               // col base in sub-block

    int st = 0;
    for (int ch = 0; ch < NCH; ++ch, st = (st == 2 ? 0 : st + 1)) {
        const int c0 = ch * CH;
        if (ch + 2 < NCH) cpa_wait1(); else cpa_wait0();
        __syncthreads();                     // stage st ready; st+2 area free

        if (ch + 2 < NCH) {
            int st2 = st + 2; if (st2 >= 3) st2 -= 3;
            prefetch(c0 + 2 * CH, st2);
        }

        const uint32_t kvb = sb + (uint32_t)st * STG;

        #pragma unroll
        for (int sc = 0; sc < NSUB; ++sc) {
            const int c0s = c0 + sc * 32;    // sub-block base column
            const int krow0 = sc * 32 + nh * 16;

            // ---- sph/mask straight to registers ---------------------------
            float2 spr[2][2]; int2 mkr[2][2];
            #pragma unroll
            for (int nt = 0; nt < 2; ++nt)
                #pragma unroll
                for (int hf = 0; hf < 2; ++hf) {
                    const size_t off = (size_t)(rt * 16 + hf * 8 + g) * SQ
                                     + c0s + cbase + nt * 8;
                    spr[nt][hf] = __ldcs((const float2*)(sc0 + off));
                    mkr[nt][hf] = __ldcs((const int2*)(mc0 + off));
                }

            // ---- QK^T for this warp's kv-half: S[2][4], 3 combos ----------
            float S[2][4];
            S[0][0] = S[0][1] = S[0][2] = S[0][3] = 0.f;
            S[1][0] = S[1][1] = S[1][2] = S[1][3] = 0.f;
            #pragma unroll
            for (int kk = 0; kk < 4; ++kk) {
                uint32_t koff = swz(krow0 + kntad * 8 + ksrow, kssel + kk * 32);
                uint32_t bh[4], bl[4];
                ldsm4(bh, kvb + koff);                // khi
                ldsm4(bl, kvb + 16384 + koff);        // klo
                mma_bf16(S[0], ah[kk], bh[0], bh[1]);
                mma_bf16(S[1], ah[kk], bh[2], bh[3]);
                mma_bf16(S[0], ah[kk], bl[0], bl[1]);
                mma_bf16(S[1], ah[kk], bl[2], bl[3]);
                mma_bf16(S[0], al[kk], bh[0], bh[1]);
                mma_bf16(S[1], al[kk], bh[2], bh[3]);
            }

            // ---- e = mask * exp(s*sph): p fp32 stores, pack e -> f16 ------
            uint32_t ea[4];
            #pragma unroll
            for (int nt = 0; nt < 2; ++nt) {
                float e0 = mkr[nt][0].x ? __expf(S[nt][0] * spr[nt][0].x) : 0.f;
                float e1 = mkr[nt][0].y ? __expf(S[nt][1] * spr[nt][0].y) : 0.f;
                float e2 = mkr[nt][1].x ? __expf(S[nt][2] * spr[nt][1].x) : 0.f;
                float e3 = mkr[nt][1].y ? __expf(S[nt][3] * spr[nt][1].y) : 0.f;
                lacc0 += e0 + e1;
                lacc1 += e2 + e3;
                const int c = c0s + cbase + nt * 8;
                *(float2*)(pc0 + (size_t)r0 * SQ + c) = make_float2(e0, e1);
                *(float2*)(pc0 + (size_t)r1 * SQ + c) = make_float2(e2, e3);
                ea[nt * 2]     = h2u(__float22half2_rn(make_float2(e0, e1)));
                ea[nt * 2 + 1] = h2u(__float22half2_rn(make_float2(e2, e3)));
            }

            // ---- PV: O_partial += E(f16) * V(f16), single combo -----------
            #pragma unroll
            for (int ntp2 = 0; ntp2 < 4; ++ntp2) {
                uint32_t voff = swz(krow0 + vrow, (ntp2 * 2 + vntad) * 16);
                uint32_t vb[4];
                ldsm4t(vb, kvb + 32768 + voff);
                mma_f16(O[2 * ntp2],     ea, vb[0], vb[1]);
                mma_f16(O[2 * ntp2 + 1], ea, vb[2], vb[3]);
            }
        }
    }

    // ---- epilogue: reduce l and O across the two kv-half warp groups ------
    lacc0 += __shfl_xor_sync(0xffffffffu, lacc0, 1);
    lacc0 += __shfl_xor_sync(0xffffffffu, lacc0, 2);
    lacc1 += __shfl_xor_sync(0xffffffffu, lacc1, 1);
    lacc1 += __shfl_xor_sync(0xffffffffu, lacc1, 2);
    __syncthreads();   // all stage reads done; smem free for osm/l_sm
    if (lam == 0) {
        l_sm[nh * 128 + r0] = lacc0;
        l_sm[nh * 128 + r1] = lacc1;
    }
    if (nh == 1) {
        float* dst = osm + ((size_t)rt * 32 + lane) * 32;
        #pragma unroll
        for (int a = 0; a < 8; ++a)
            *(float4*)(dst + a * 4) =
                make_float4(O[a][0], O[a][1], O[a][2], O[a][3]);
    }
    __syncthreads();
    if (nh == 0) {
        const float* src = osm + ((size_t)rt * 32 + lane) * 32;
        #pragma unroll
        for (int a = 0; a < 8; ++a) {
            float4 x = *(const float4*)(src + a * 4);
            O[a][0] += x.x; O[a][1] += x.y; O[a][2] += x.z; O[a][3] += x.w;
        }
        const float inv0 = 1.0f / (l_sm[r0] + l_sm[128 + r0]);
        const float inv1 = 1.0f / (l_sm[r1] + l_sm[128 + r1]);
        float* o0 = out + ((size_t)h * SQ + q0 + r0) * HD;
        float* o1 = out + ((size_t)h * SQ + q0 + r1) * HD;
        #pragma unroll
        for (int nt2 = 0; nt2 < 8; ++nt2) {
            const int d = nt2 * 8 + lam * 2;
            *(float2*)(o0 + d) = make_float2(O[nt2][0] * inv0, O[nt2][1] * inv0);
            *(float2*)(o1 + d) = make_float2(O[nt2][2] * inv1, O[nt2][3] * inv1);
        }
    }

    // ---- fused p normalization: each warp rescales its 8 rows (L2-hot) ----
    #pragma unroll 1
    for (int rr = 0; rr < 8; ++rr) {
        const int row = w * 8 + rr;
        const float inv = 1.0f / (l_sm[row] + l_sm[128 + row]);
        float4* pr = (float4*)(pc0 + (size_t)row * SQ);
        #pragma unroll
        for (int i = lane; i < SQ / 4; i += 32) {
            float4 x = __ldcg((const float4*)(pr + i));
            x.x *= inv; x.y *= inv; x.z *= inv; x.w *= inv;
            __stcs((float4*)(pr + i), x);
        }
    }
}

extern "C" void kernel_launch(void* const* d_in, const int* in_sizes, int n_in,
                              void* d_out, int out_size)
{
    const float* q    = (const float*)d_in[0];
    const float* k    = (const float*)d_in[1];
    const float* v    = (const float*)d_in[2];
    const float* sph  = (const float*)d_in[3];
    const int*   mask = (const int*)d_in[4];

    float* out = (float*)d_out;                 // [1,8,2048,64]
    float* p   = out + (size_t)NH * SQ * HD;    // [1,8,2048,2048]

    cudaFuncSetAttribute(attn_mma, cudaFuncAttributeMaxDynamicSharedMemorySize,
                         S_TOTAL);

    conv_kv<<<NH * SQ * HD / 4 / 256, 256>>>(k, v);
    dim3 grid(SQ / MT, NH);
    attn_mma<<<grid, THREADS, S_TOTAL>>>(q, sph, mask, out, p);
}

// round 14
// speedup vs baseline: 1.2204x; 1.2204x over previous
#include <cuda_runtime.h>
#include <cuda_bf16.h>
#include <cuda_fp16.h>
#include <cstdint>

// ScaledDotProductAttention B=1 H=8 S=2048 D=64, sm_103 base ISA.
// R12 math at MT=64 / 256 threads / 2 CTAs-per-SM: grid 256 fills all 148
// SMs in one wave (previous rounds left 20 SMs idle). CH=32, 3-stage
// KV-only cp.async pipeline; sph/mask straight to registers; V single f16
// (PV 1 combo); QK bf16 hi/lo 3-combo; fp32 unnormalized p in-loop; fused
// tail normalizes p. d_out = [out 1x8x2048x64 | p_attn 1x8x2048x2048].

#define SQ 2048
#define HD 64
#define NH 8
#define MT 64           // q rows per CTA
#define CH 32           // kv per chunk
#define NCH (SQ / CH)   // 64
#define THREADS 256

// ---- smem layout (bytes) ----
// stage s at s*STG: khi 0 | klo 4096 | vh 8192   (12KB each, 3 stages)
#define STG   12288
#define S_QHI 36864                      // Q hi 8KB (prologue only)
#define S_QLO 45056                      // Q lo 8KB
#define S_TOTAL 53248
// epilogue overlays (stage area)
#define S_OSM 0                          // f32 [4][32][32] = 16KB
#define S_LSM 16384                      // f32 [2][64]

__device__ __nv_bfloat16 g_khi[NH * SQ * HD];
__device__ __nv_bfloat16 g_klo[NH * SQ * HD];
__device__ __half        g_vh [NH * SQ * HD];

__device__ __forceinline__ uint32_t smem_u32(const void* p) {
    uint32_t a;
    asm("{ .reg .u64 t; cvta.to.shared.u64 t, %1; cvt.u32.u64 %0, t; }"
        : "=r"(a) : "l"(p));
    return a;
}
__device__ __forceinline__ void cpa16(uint32_t dst, const void* src) {
    asm volatile("cp.async.cg.shared.global [%0], [%1], 16;"
                 :: "r"(dst), "l"(src));
}
__device__ __forceinline__ void cpa_commit() {
    asm volatile("cp.async.commit_group;" ::: "memory");
}
__device__ __forceinline__ void cpa_wait0() {
    asm volatile("cp.async.wait_group 0;" ::: "memory");
}
__device__ __forceinline__ void cpa_wait1() {
    asm volatile("cp.async.wait_group 1;" ::: "memory");
}
__device__ __forceinline__ void ldsm4(uint32_t* r, uint32_t addr) {
    asm volatile("ldmatrix.sync.aligned.m8n8.x4.shared.b16 {%0,%1,%2,%3}, [%4];"
                 : "=r"(r[0]), "=r"(r[1]), "=r"(r[2]), "=r"(r[3]) : "r"(addr));
}
__device__ __forceinline__ void ldsm4t(uint32_t* r, uint32_t addr) {
    asm volatile("ldmatrix.sync.aligned.m8n8.x4.trans.shared.b16 {%0,%1,%2,%3}, [%4];"
                 : "=r"(r[0]), "=r"(r[1]), "=r"(r[2]), "=r"(r[3]) : "r"(addr));
}
__device__ __forceinline__ void mma_bf16(float* c, const uint32_t* a,
                                         uint32_t b0, uint32_t b1) {
    asm volatile(
        "mma.sync.aligned.m16n8k16.row.col.f32.bf16.bf16.f32 "
        "{%0,%1,%2,%3}, {%4,%5,%6,%7}, {%8,%9}, {%0,%1,%2,%3};"
        : "+f"(c[0]), "+f"(c[1]), "+f"(c[2]), "+f"(c[3])
        : "r"(a[0]), "r"(a[1]), "r"(a[2]), "r"(a[3]), "r"(b0), "r"(b1));
}
__device__ __forceinline__ void mma_f16(float* c, const uint32_t* a,
                                        uint32_t b0, uint32_t b1) {
    asm volatile(
        "mma.sync.aligned.m16n8k16.row.col.f32.f16.f16.f32 "
        "{%0,%1,%2,%3}, {%4,%5,%6,%7}, {%8,%9}, {%0,%1,%2,%3};"
        : "+f"(c[0]), "+f"(c[1]), "+f"(c[2]), "+f"(c[3])
        : "r"(a[0]), "r"(a[1]), "r"(a[2]), "r"(a[3]), "r"(b0), "r"(b1));
}
__device__ __forceinline__ uint32_t bf2u(__nv_bfloat162 x) {
    uint32_t r; *(__nv_bfloat162*)&r = x; return r;
}
__device__ __forceinline__ void split_pack2(float a, float b,
                                            uint32_t& hi, uint32_t& lo) {
    __nv_bfloat162 h = __floats2bfloat162_rn(a, b);
    hi = bf2u(h);
    lo = bf2u(__floats2bfloat162_rn(a - __bfloat162float(h.x),
                                    b - __bfloat162float(h.y)));
}
__device__ __forceinline__ uint32_t h2u(__half2 x) {
    uint32_t r; *(__half2*)&r = x; return r;
}
// 128B-row tiles: SW128-style swizzle
__device__ __forceinline__ uint32_t swz(int row, int colB) {
    return (uint32_t)(((row << 7) + colB) ^ ((row & 7) << 4));
}

// ---------------- prep: K -> bf16 hi/lo, V -> f16 ----------------
__global__ __launch_bounds__(256)
void conv_kv(const float* __restrict__ k, const float* __restrict__ v)
{
    int idx = blockIdx.x * 256 + threadIdx.x;   // over NH*SQ*HD/4
    float4 kf = ((const float4*)k)[idx];
    uint32_t h0, l0, h1, l1;
    split_pack2(kf.x, kf.y, h0, l0);
    split_pack2(kf.z, kf.w, h1, l1);
    ((uint2*)g_khi)[idx] = make_uint2(h0, h1);
    ((uint2*)g_klo)[idx] = make_uint2(l0, l1);
    float4 vf = ((const float4*)v)[idx];
    __half2 v0 = __float22half2_rn(make_float2(vf.x, vf.y));
    __half2 v1 = __float22half2_rn(make_float2(vf.z, vf.w));
    ((uint2*)g_vh)[idx] = make_uint2(h2u(v0), h2u(v1));
}

// ---------------- main fused attention (+ p normalization) ----------------
__global__ __launch_bounds__(THREADS, 2)
void attn_mma(const float* __restrict__ q, const float* __restrict__ sph,
              const int* __restrict__ mask,
              float* __restrict__ out, float* __restrict__ p)
{
    extern __shared__ char smem[];
    const uint32_t sb = smem_u32(smem);
    float* osm  = (float*)(smem + S_OSM);
    float* l_sm = (float*)(smem + S_LSM);

    const int t = threadIdx.x, w = t >> 5, lane = t & 31;
    const int g = lane >> 2, lam = lane & 3;
    const int rt = w & 3;              // row-tile (16 rows, 4 tiles = 64)
    const int nh = w >> 2;             // kv-half of the 32-chunk
    const int h = blockIdx.y, q0 = blockIdx.x * MT;
    const int r0 = rt * 16 + g, r1 = r0 + 8;

    const float* qh  = q + ((size_t)h * SQ + q0) * HD;
    const float* sc0 = sph + ((size_t)h * SQ + q0) * SQ;
    const int*   mc0 = mask + ((size_t)h * SQ + q0) * SQ;
    float*       pc0 = p + ((size_t)h * SQ + q0) * SQ;

    const __nv_bfloat16* kh = g_khi + (size_t)h * SQ * HD;
    const __nv_bfloat16* kl = g_klo + (size_t)h * SQ * HD;
    const __half*        vv = g_vh  + (size_t)h * SQ * HD;

    // KV-only stage prefetch: 768 16B units (khi 256 | klo 256 | vh 256)
    auto prefetch = [&](int cc, int st) {
        const uint32_t base = sb + (uint32_t)st * STG;
        #pragma unroll
        for (int it = 0; it < 3; ++it) {
            int idx = t + THREADS * it;         // 0..767 exactly
            int arr = idx >> 8;
            int rem = idx & 255, row = rem >> 3, u = rem & 7;
            const void* src = (arr == 0)
                ? (const void*)(kh + (size_t)(cc + row) * HD + u * 8)
                : (arr == 1)
                ? (const void*)(kl + (size_t)(cc + row) * HD + u * 8)
                : (const void*)(vv + (size_t)(cc + row) * HD + u * 8);
            cpa16(base + arr * 4096 + swz(row, u * 16), src);
        }
        cpa_commit();
    };

    prefetch(0, 0);
    prefetch(CH, 1);

    // ---- prologue: stage Q (x1/8) hi/lo, load A-frags into registers ----
    #pragma unroll
    for (int i = 0; i < 4; ++i) {                // 1024 float4 = 64x64
        int idx = t + THREADS * i;
        int row = idx >> 4, gq = idx & 15;
        float4 f = ((const float4*)qh)[idx];
        f.x *= 0.125f; f.y *= 0.125f; f.z *= 0.125f; f.w *= 0.125f;
        uint32_t h0, l0, h1, l1;
        split_pack2(f.x, f.y, h0, l0);
        split_pack2(f.z, f.w, h1, l1);
        uint32_t off = swz(row, gq * 8);
        *(uint2*)(smem + S_QHI + off) = make_uint2(h0, h1);
        *(uint2*)(smem + S_QLO + off) = make_uint2(l0, l1);
    }
    __syncthreads();
    uint32_t ah[4][4], al[4][4];
    {
        int arow = rt * 16 + ((lane >> 3) & 1) * 8 + (lane & 7);
        int acol = ((lane >> 4) & 1) * 16;
        #pragma unroll
        for (int kk = 0; kk < 4; ++kk) {
            uint32_t aoff = swz(arow, acol + kk * 32);
            ldsm4(ah[kk], sb + S_QHI + aoff);
            ldsm4(al[kk], sb + S_QLO + aoff);
        }
    }

    float O[8][4];
    #pragma unroll
    for (int a = 0; a < 8; ++a)
        #pragma unroll
        for (int b = 0; b < 4; ++b) O[a][b] = 0.f;
    float lacc0 = 0.f, lacc1 = 0.f;

    const int ksrow = (lane & 7);                      // K ldsm row-in-tile
    const int kssel = ((lane >> 3) & 1) * 16;
    const int kntad = (lane >> 4);                     // +0/+1 n-tile
    const int vrow  = (lane & 15);                     // V ldsm
    const int vntad = (lane >> 4);
    const int cbase = nh * 16 + lam * 2;               // this thread's col base

    int st = 0;
    for (int ch = 0; ch < NCH; ++ch, st = (st == 2 ? 0 : st + 1)) {
        const int c0 = ch * CH;

        // ---- sph/mask straight to registers (overlaps wait + QK) ----------
        float2 spr[2][2]; int2 mkr[2][2];
        #pragma unroll
        for (int nt = 0; nt < 2; ++nt)
            #pragma unroll
            for (int hf = 0; hf < 2; ++hf) {
                const size_t off = (size_t)(rt * 16 + hf * 8 + g) * SQ
                                 + c0 + cbase + nt * 8;
                spr[nt][hf] = __ldcs((const float2*)(sc0 + off));
                mkr[nt][hf] = __ldcs((const int2*)(mc0 + off));
            }

        if (ch + 2 < NCH) cpa_wait1(); else cpa_wait0();
        __syncthreads();

        if (ch + 2 < NCH) {
            int st2 = st + 2; if (st2 >= 3) st2 -= 3;
            prefetch(c0 + 2 * CH, st2);
        }

        const uint32_t kvb = sb + (uint32_t)st * STG;

        // ---- QK^T for this warp's kv-half: S[2][4], 3 combos --------------
        float S[2][4];
        S[0][0] = S[0][1] = S[0][2] = S[0][3] = 0.f;
        S[1][0] = S[1][1] = S[1][2] = S[1][3] = 0.f;
        #pragma unroll
        for (int kk = 0; kk < 4; ++kk) {
            uint32_t koff = swz(nh * 16 + kntad * 8 + ksrow, kssel + kk * 32);
            uint32_t bh[4], bl[4];
            ldsm4(bh, kvb + koff);            // khi
            ldsm4(bl, kvb + 4096 + koff);     // klo
            mma_bf16(S[0], ah[kk], bh[0], bh[1]);
            mma_bf16(S[1], ah[kk], bh[2], bh[3]);
            mma_bf16(S[0], ah[kk], bl[0], bl[1]);
            mma_bf16(S[1], ah[kk], bl[2], bl[3]);
            mma_bf16(S[0], al[kk], bh[0], bh[1]);
            mma_bf16(S[1], al[kk], bh[2], bh[3]);
        }

        // ---- e = mask * exp(s*sph): p fp32 stores, pack e -> f16 frags -----
        uint32_t ea[4];
        #pragma unroll
        for (int nt = 0; nt < 2; ++nt) {
            float e0 = mkr[nt][0].x ? __expf(S[nt][0] * spr[nt][0].x) : 0.f;
            float e1 = mkr[nt][0].y ? __expf(S[nt][1] * spr[nt][0].y) : 0.f;
            float e2 = mkr[nt][1].x ? __expf(S[nt][2] * spr[nt][1].x) : 0.f;
            float e3 = mkr[nt][1].y ? __expf(S[nt][3] * spr[nt][1].y) : 0.f;
            lacc0 += e0 + e1;
            lacc1 += e2 + e3;
            const int c = c0 + cbase + nt * 8;
            *(float2*)(pc0 + (size_t)r0 * SQ + c) = make_float2(e0, e1);
            *(float2*)(pc0 + (size_t)r1 * SQ + c) = make_float2(e2, e3);
            ea[nt * 2]     = h2u(__float22half2_rn(make_float2(e0, e1)));
            ea[nt * 2 + 1] = h2u(__float22half2_rn(make_float2(e2, e3)));
        }

        // ---- PV: O_partial += E(f16) * V(f16), single combo ----------------
        #pragma unroll
        for (int ntp2 = 0; ntp2 < 4; ++ntp2) {
            uint32_t voff = swz(nh * 16 + vrow, (ntp2 * 2 + vntad) * 16);
            uint32_t vb[4];
            ldsm4t(vb, kvb + 8192 + voff);
            mma_f16(O[2 * ntp2],     ea, vb[0], vb[1]);
            mma_f16(O[2 * ntp2 + 1], ea, vb[2], vb[3]);
        }
    }

    // ---- epilogue: reduce l and O across the two kv-half warp groups ------
    lacc0 += __shfl_xor_sync(0xffffffffu, lacc0, 1);
    lacc0 += __shfl_xor_sync(0xffffffffu, lacc0, 2);
    lacc1 += __shfl_xor_sync(0xffffffffu, lacc1, 1);
    lacc1 += __shfl_xor_sync(0xffffffffu, lacc1, 2);
    __syncthreads();   // all stage reads done; smem free for osm/l_sm
    if (lam == 0) {
        l_sm[nh * 64 + r0] = lacc0;
        l_sm[nh * 64 + r1] = lacc1;
    }
    if (nh == 1) {
        float* dst = osm + ((size_t)rt * 32 + lane) * 32;
        #pragma unroll
        for (int a = 0; a < 8; ++a)
            *(float4*)(dst + a * 4) =
                make_float4(O[a][0], O[a][1], O[a][2], O[a][3]);
    }
    __syncthreads();
    if (nh == 0) {
        const float* src = osm + ((size_t)rt * 32 + lane) * 32;
        #pragma unroll
        for (int a = 0; a < 8; ++a) {
            float4 x = *(const float4*)(src + a * 4);
            O[a][0] += x.x; O[a][1] += x.y; O[a][2] += x.z; O[a][3] += x.w;
        }
        const float inv0 = 1.0f / (l_sm[r0] + l_sm[64 + r0]);
        const float inv1 = 1.0f / (l_sm[r1] + l_sm[64 + r1]);
        float* o0 = out + ((size_t)h * SQ + q0 + r0) * HD;
        float* o1 = out + ((size_t)h * SQ + q0 + r1) * HD;
        #pragma unroll
        for (int nt2 = 0; nt2 < 8; ++nt2) {
            const int d = nt2 * 8 + lam * 2;
            *(float2*)(o0 + d) = make_float2(O[nt2][0] * inv0, O[nt2][1] * inv0);
            *(float2*)(o1 + d) = make_float2(O[nt2][2] * inv1, O[nt2][3] * inv1);
        }
    }

    // ---- fused p normalization: each warp rescales its 8 rows (L2-hot) ----
    #pragma unroll 1
    for (int rr = 0; rr < 8; ++rr) {
        const int row = w * 8 + rr;
        const float inv = 1.0f / (l_sm[row] + l_sm[64 + row]);
        float4* pr = (float4*)(pc0 + (size_t)row * SQ);
        #pragma unroll
        for (int i = lane; i < SQ / 4; i += 32) {
            float4 x = __ldcg((const float4*)(pr + i));
            x.x *= inv; x.y *= inv; x.z *= inv; x.w *= inv;
            __stcs((float4*)(pr + i), x);
        }
    }
}

extern "C" void kernel_launch(void* const* d_in, const int* in_sizes, int n_in,
                              void* d_out, int out_size)
{
    const float* q    = (const float*)d_in[0];
    const float* k    = (const float*)d_in[1];
    const float* v    = (const float*)d_in[2];
    const float* sph  = (const float*)d_in[3];
    const int*   mask = (const int*)d_in[4];

    float* out = (float*)d_out;                 // [1,8,2048,64]
    float* p   = out + (size_t)NH * SQ * HD;    // [1,8,2048,2048]

    cudaFuncSetAttribute(attn_mma, cudaFuncAttributeMaxDynamicSharedMemorySize,
                         S_TOTAL);

    conv_kv<<<NH * SQ * HD / 4 / 256, 256>>>(k, v);
    dim3 grid(SQ / MT, NH);
    attn_mma<<<grid, THREADS, S_TOTAL>>>(q, sph, mask, out, p);
}